// round 14
// baseline (speedup 1.0000x reference)
#include <cuda_runtime.h>
#include <cuda_bf16.h>

// T=50, H=W=8, NH=16, B=8, TP=TF=8, HIDDEN=512, RPE_COEF=16
#define NROW   22275          // 99*15*15
#define NROWP  22400          // 350 blocks * 64 rows
#define NHEAD  16
#define HIDDEN 512
#define W2TS   520            // bf16 row stride for transposed W2 (conflict-free)

// Scratch: g_rpt[nh][row] = 16*sigmoid( (relu(rct@W1+b1)@W2)[row][nh] )
__device__ float g_rpt[NHEAD * NROWP];

// pack two fp32 -> bf16x2 (FIRST arg in low 16 bits)
__device__ __forceinline__ unsigned bfpack(float lo, float hi) {
    unsigned r;
    asm("cvt.rn.bf16x2.f32 %0, %1, %2;" : "=r"(r) : "f"(hi), "f"(lo));
    return r;
}

// ---------------------------------------------------------------------------
// Kernel 1: FUSED cpb MLP with tensor-core layer 2 (R10 core) + vectorized
// weight staging (the R10 prologue was ~half the kernel's cost).
//  Block 128 thr = 4 warps; warp w owns rows [row0 + 16w, +16).
//  Staging: W2 transposed to bf16 via LDG.128 row pairs + bf16x2 pair-pack
//  (low half = even k -> exact b-fragment byte order), STS.32 per n.
// ---------------------------------------------------------------------------
__global__ void __launch_bounds__(128) mlp_kernel(
    const float* __restrict__ rct,   // [NROW, 3]
    const float* __restrict__ W1,    // [3, 512]
    const float* __restrict__ b1,    // [512]
    const float* __restrict__ W2)    // [512, 16]
{
    __shared__ float4 sW14[HIDDEN];                       // 8 KB  {W1_0,W1_1,W1_2,b1}[h]
    __shared__ __align__(16) __nv_bfloat16 sW2T[NHEAD * W2TS];  // 16.25 KB  [n][k]

    const int tid  = threadIdx.x;
    const int wid  = tid >> 5;
    const int lane = tid & 31;
    const int g    = lane >> 2;          // 0..7
    const int t    = lane & 3;           // 0..3
    const int row0 = blockIdx.x * 64;

    // Stage W1|b1 (4 coalesced scalar streams per entry)
    #pragma unroll
    for (int i = tid; i < HIDDEN; i += 128)
        sW14[i] = make_float4(__ldg(W1 + i), __ldg(W1 + HIDDEN + i),
                              __ldg(W1 + 2 * HIDDEN + i), __ldg(b1 + i));

    // Stage W2 transposed bf16: thread handles k-pairs (2 pairs): vectorized.
    {
        const float4* __restrict__ w2v = reinterpret_cast<const float4*>(W2);
        #pragma unroll
        for (int pr = tid; pr < 256; pr += 128) {        // k-pair index, k0 = 2*pr
            const int k0 = 2 * pr;
            float a[16], b[16];
            #pragma unroll
            for (int q = 0; q < 4; q++) {
                const float4 ra = __ldg(w2v + k0 * 4 + q);        // W2[k0][4q..4q+3]
                const float4 rb = __ldg(w2v + (k0 + 1) * 4 + q);  // W2[k0+1][..]
                a[4*q+0] = ra.x; a[4*q+1] = ra.y; a[4*q+2] = ra.z; a[4*q+3] = ra.w;
                b[4*q+0] = rb.x; b[4*q+1] = rb.y; b[4*q+2] = rb.z; b[4*q+3] = rb.w;
            }
            #pragma unroll
            for (int n = 0; n < 16; n++)
                *reinterpret_cast<unsigned*>(&sW2T[n * W2TS + k0]) = bfpack(a[n], b[n]);
        }
    }

    const int rw = row0 + wid * 16;
    const int r0 = rw + g, r1 = r0 + 8;
    float cA0 = 0.f, cA1 = 0.f, cA2 = 0.f, cB0 = 0.f, cB1 = 0.f, cB2 = 0.f;
    if (r0 < NROW) { cA0 = __ldg(rct + r0 * 3 + 0);
                     cA1 = __ldg(rct + r0 * 3 + 1);
                     cA2 = __ldg(rct + r0 * 3 + 2); }
    if (r1 < NROW) { cB0 = __ldg(rct + r1 * 3 + 0);
                     cB1 = __ldg(rct + r1 * 3 + 1);
                     cB2 = __ldg(rct + r1 * 3 + 2); }
    __syncthreads();

    float d0[4] = {0.f, 0.f, 0.f, 0.f};   // nh 0-7 tile
    float d1[4] = {0.f, 0.f, 0.f, 0.f};   // nh 8-15 tile

    #pragma unroll 4
    for (int ch = 0; ch < 32; ch++) {
        const int h0 = ch * 16 + 2 * t;   // k positions: h0, h0+1, h0+8, h0+9
        float hA[4], hB[4];
        #pragma unroll
        for (int q = 0; q < 4; q++) {
            const int h = h0 + (q & 1) + (q >> 1) * 8;
            const float4 wc = sW14[h];
            hA[q] = fmaxf(fmaf(cA2, wc.z, fmaf(cA1, wc.y, fmaf(cA0, wc.x, wc.w))), 0.f);
            hB[q] = fmaxf(fmaf(cB2, wc.z, fmaf(cB1, wc.y, fmaf(cB0, wc.x, wc.w))), 0.f);
        }
        const unsigned a0 = bfpack(hA[0], hA[1]);
        const unsigned a1 = bfpack(hB[0], hB[1]);
        const unsigned a2 = bfpack(hA[2], hA[3]);
        const unsigned a3 = bfpack(hB[2], hB[3]);
        const unsigned bA0 = *reinterpret_cast<const unsigned*>(&sW2T[g * W2TS + h0]);
        const unsigned bA1 = *reinterpret_cast<const unsigned*>(&sW2T[g * W2TS + h0 + 8]);
        const unsigned bB0 = *reinterpret_cast<const unsigned*>(&sW2T[(g + 8) * W2TS + h0]);
        const unsigned bB1 = *reinterpret_cast<const unsigned*>(&sW2T[(g + 8) * W2TS + h0 + 8]);
        asm volatile(
            "mma.sync.aligned.m16n8k16.row.col.f32.bf16.bf16.f32 "
            "{%0,%1,%2,%3}, {%4,%5,%6,%7}, {%8,%9}, {%0,%1,%2,%3};"
            : "+f"(d0[0]), "+f"(d0[1]), "+f"(d0[2]), "+f"(d0[3])
            : "r"(a0), "r"(a1), "r"(a2), "r"(a3), "r"(bA0), "r"(bA1));
        asm volatile(
            "mma.sync.aligned.m16n8k16.row.col.f32.bf16.bf16.f32 "
            "{%0,%1,%2,%3}, {%4,%5,%6,%7}, {%8,%9}, {%0,%1,%2,%3};"
            : "+f"(d1[0]), "+f"(d1[1]), "+f"(d1[2]), "+f"(d1[3])
            : "r"(a0), "r"(a1), "r"(a2), "r"(a3), "r"(bB0), "r"(bB1));
    }

    #pragma unroll
    for (int j = 0; j < 4; j++) {
        d0[j] = 16.f / (1.f + __expf(-d0[j]));
        d1[j] = 16.f / (1.f + __expf(-d1[j]));
    }
    const int nh0 = 2 * t;
    g_rpt[(nh0    ) * NROWP + r0] = d0[0];
    g_rpt[(nh0 + 1) * NROWP + r0] = d0[1];
    g_rpt[(nh0    ) * NROWP + r1] = d0[2];
    g_rpt[(nh0 + 1) * NROWP + r1] = d0[3];
    g_rpt[(nh0 + 8) * NROWP + r0] = d1[0];
    g_rpt[(nh0 + 9) * NROWP + r0] = d1[1];
    g_rpt[(nh0 + 8) * NROWP + r1] = d1[2];
    g_rpt[(nh0 + 9) * NROWP + r1] = d1[3];
}

// ---------------------------------------------------------------------------
// Kernel 2: gather (confirmed at the output-write floor; R8/R10 version).
// One block per (b, nh, tf, tp) 64x64 tile; vtab holds the 240 distinct
// output float4s; hot loop = 1 LDS.128 + 1 streaming STG.128.
//   idx = (t_f + t_p)*225 + (hf-hp+7)*15 + (wf-wp+7)
// ---------------------------------------------------------------------------
__global__ void __launch_bounds__(256) gather_kernel(
    const int* __restrict__ ptc,     // [B, 8] (non-positive; time = -ptc)
    const int* __restrict__ ftc,     // [B, 8]
    float4* __restrict__ out)        // [B, 16, 512, 512] / 4
{
    __shared__ float4 vtab[240];     // [wf][dh+7][par] : wf*30 + dh7*2 + par
    const int tid = threadIdx.x;
    const int blk = blockIdx.x;
    const int tp = blk & 7;
    const int tf = (blk >> 3) & 7;
    const int nh = (blk >> 6) & 15;
    const int b  = blk >> 10;

    const int t_f =  __ldg(ftc + b * 8 + tf);
    const int t_p = -__ldg(ptc + b * 8 + tp);
    const float* __restrict__ src = g_rpt + nh * NROWP + (t_f + t_p) * 225;

    if (tid < 240) {
        const int wf  = tid / 30;
        const int rem = tid - wf * 30;
        const int dh7 = rem >> 1;
        const int par = rem & 1;                       // wp0 = par*4
        const int si  = dh7 * 15 + wf - par * 4 + 7;   // in [3, 224]
        vtab[tid] = make_float4(__ldg(src + si),     __ldg(src + si - 1),
                                __ldg(src + si - 2), __ldg(src + si - 3));
    }
    __syncthreads();

    const int c4    = tid & 15;
    const int fhw0  = tid >> 4;            // 0..15
    const int wf    = fhw0 & 7;
    const int b0    = fhw0 >> 3;           // 0 or 1
    const int hp    = c4 >> 1;
    const int par   = c4 & 1;
    const int base0 = wf * 30 + (b0 - hp + 7) * 2 + par;   // k=0 index

    float4* __restrict__ p =
        out + ((((b * NHEAD + nh) * 512 + tf * 64) * 512 + tp * 64) >> 2)
            + fhw0 * 128 + c4;

    #pragma unroll
    for (int k = 0; k < 4; k++) {
        __stcs(p, vtab[base0 + 4 * k]);    // hf = b0 + 2k, always <= 7
        p += 2048;                          // fhw += 16
    }
}

// ---------------------------------------------------------------------------
// Launch. Input order: ptc, ftc, W1, b1, W2, rct, rpi_table (unused).
// ---------------------------------------------------------------------------
extern "C" void kernel_launch(void* const* d_in, const int* in_sizes, int n_in,
                              void* d_out, int out_size)
{
    const int*   ptc = (const int*)  d_in[0];
    const int*   ftc = (const int*)  d_in[1];
    const float* W1  = (const float*)d_in[2];
    const float* b1  = (const float*)d_in[3];
    const float* W2  = (const float*)d_in[4];
    const float* rct = (const float*)d_in[5];

    // 350 blocks x 64 rows = 22400 (NROWP); rows >= NROW are never read.
    mlp_kernel<<<NROWP / 64, 128>>>(rct, W1, b1, W2);

    // 8192 blocks: one per (b, nh, tf, tp) 64x64 tile
    gather_kernel<<<8 * NHEAD * 8 * 8, 256>>>(ptc, ftc, (float4*)d_out);
}

// round 16
// speedup vs baseline: 1.0636x; 1.0636x over previous
#include <cuda_runtime.h>
#include <cuda_bf16.h>

// T=50, H=W=8, NH=16, B=8, TP=TF=8, HIDDEN=512, RPE_COEF=16
#define NROW   22275          // 99*15*15
#define NROWP  22400          // 175 blocks * 128 rows
#define NHEAD  16
#define HIDDEN 512
#define W2TS   520            // bf16 row stride for transposed W2 (conflict-free)

// Scratch: g_rpt[nh][row] = 16*sigmoid( (relu(rct@W1+b1)@W2)[row][nh] )
__device__ float g_rpt[NHEAD * NROWP];

// pack two fp32 -> bf16x2 (FIRST arg in low 16 bits)
__device__ __forceinline__ unsigned bfpack(float lo, float hi) {
    unsigned r;
    asm("cvt.rn.bf16x2.f32 %0, %1, %2;" : "=r"(r) : "f"(hi), "f"(lo));
    return r;
}

// ---------------------------------------------------------------------------
// Kernel 1: FUSED cpb MLP with tensor-core layer 2 (R10 core, R10 scalar
// staging). 175 blocks x 256 thr (8 warps x 16 rows = 128 rows/block):
// same per-block staging cost as R10 but HALF the blocks -> chip staging
// traffic halves while the HMMA main loop stays latency-flat.
// ---------------------------------------------------------------------------
__global__ void __launch_bounds__(256) mlp_kernel(
    const float* __restrict__ rct,   // [NROW, 3]
    const float* __restrict__ W1,    // [3, 512]
    const float* __restrict__ b1,    // [512]
    const float* __restrict__ W2)    // [512, 16]
{
    __shared__ float4 sW14[HIDDEN];                       // 8 KB  {W1_0,W1_1,W1_2,b1}[h]
    __shared__ __align__(16) __nv_bfloat16 sW2T[NHEAD * W2TS];  // 16.25 KB  [n][k]

    const int tid  = threadIdx.x;
    const int wid  = tid >> 5;           // 0..7, warp -> 16 rows
    const int lane = tid & 31;
    const int g    = lane >> 2;          // 0..7
    const int t    = lane & 3;           // 0..3
    const int row0 = blockIdx.x * 128;

    // Stage W1|b1 (R10 scalar form; 2 iterations at 256 threads)
    #pragma unroll
    for (int i = tid; i < HIDDEN; i += 256)
        sW14[i] = make_float4(__ldg(W1 + i), __ldg(W1 + HIDDEN + i),
                              __ldg(W1 + 2 * HIDDEN + i), __ldg(b1 + i));
    // Stage W2 transposed as bf16: sW2T[n][k] (R10 scalar form; 32 iterations)
    #pragma unroll
    for (int i = tid; i < HIDDEN * NHEAD; i += 256) {
        const int k = i >> 4, n = i & 15;
        sW2T[n * W2TS + k] = __float2bfloat16(__ldg(W2 + k * NHEAD + n));
    }

    const int rw = row0 + wid * 16;
    const int r0 = rw + g, r1 = r0 + 8;
    float cA0 = 0.f, cA1 = 0.f, cA2 = 0.f, cB0 = 0.f, cB1 = 0.f, cB2 = 0.f;
    if (r0 < NROW) { cA0 = __ldg(rct + r0 * 3 + 0);
                     cA1 = __ldg(rct + r0 * 3 + 1);
                     cA2 = __ldg(rct + r0 * 3 + 2); }
    if (r1 < NROW) { cB0 = __ldg(rct + r1 * 3 + 0);
                     cB1 = __ldg(rct + r1 * 3 + 1);
                     cB2 = __ldg(rct + r1 * 3 + 2); }
    __syncthreads();

    float d0[4] = {0.f, 0.f, 0.f, 0.f};   // nh 0-7 tile
    float d1[4] = {0.f, 0.f, 0.f, 0.f};   // nh 8-15 tile

    #pragma unroll 4
    for (int ch = 0; ch < 32; ch++) {
        const int h0 = ch * 16 + 2 * t;   // k positions: h0, h0+1, h0+8, h0+9
        float hA[4], hB[4];
        #pragma unroll
        for (int q = 0; q < 4; q++) {
            const int h = h0 + (q & 1) + (q >> 1) * 8;
            const float4 wc = sW14[h];
            hA[q] = fmaxf(fmaf(cA2, wc.z, fmaf(cA1, wc.y, fmaf(cA0, wc.x, wc.w))), 0.f);
            hB[q] = fmaxf(fmaf(cB2, wc.z, fmaf(cB1, wc.y, fmaf(cB0, wc.x, wc.w))), 0.f);
        }
        const unsigned a0 = bfpack(hA[0], hA[1]);
        const unsigned a1 = bfpack(hB[0], hB[1]);
        const unsigned a2 = bfpack(hA[2], hA[3]);
        const unsigned a3 = bfpack(hB[2], hB[3]);
        const unsigned bA0 = *reinterpret_cast<const unsigned*>(&sW2T[g * W2TS + h0]);
        const unsigned bA1 = *reinterpret_cast<const unsigned*>(&sW2T[g * W2TS + h0 + 8]);
        const unsigned bB0 = *reinterpret_cast<const unsigned*>(&sW2T[(g + 8) * W2TS + h0]);
        const unsigned bB1 = *reinterpret_cast<const unsigned*>(&sW2T[(g + 8) * W2TS + h0 + 8]);
        asm volatile(
            "mma.sync.aligned.m16n8k16.row.col.f32.bf16.bf16.f32 "
            "{%0,%1,%2,%3}, {%4,%5,%6,%7}, {%8,%9}, {%0,%1,%2,%3};"
            : "+f"(d0[0]), "+f"(d0[1]), "+f"(d0[2]), "+f"(d0[3])
            : "r"(a0), "r"(a1), "r"(a2), "r"(a3), "r"(bA0), "r"(bA1));
        asm volatile(
            "mma.sync.aligned.m16n8k16.row.col.f32.bf16.bf16.f32 "
            "{%0,%1,%2,%3}, {%4,%5,%6,%7}, {%8,%9}, {%0,%1,%2,%3};"
            : "+f"(d1[0]), "+f"(d1[1]), "+f"(d1[2]), "+f"(d1[3])
            : "r"(a0), "r"(a1), "r"(a2), "r"(a3), "r"(bB0), "r"(bB1));
    }

    #pragma unroll
    for (int j = 0; j < 4; j++) {
        d0[j] = 16.f / (1.f + __expf(-d0[j]));
        d1[j] = 16.f / (1.f + __expf(-d1[j]));
    }
    const int nh0 = 2 * t;
    g_rpt[(nh0    ) * NROWP + r0] = d0[0];
    g_rpt[(nh0 + 1) * NROWP + r0] = d0[1];
    g_rpt[(nh0    ) * NROWP + r1] = d0[2];
    g_rpt[(nh0 + 1) * NROWP + r1] = d0[3];
    g_rpt[(nh0 + 8) * NROWP + r0] = d1[0];
    g_rpt[(nh0 + 9) * NROWP + r0] = d1[1];
    g_rpt[(nh0 + 8) * NROWP + r1] = d1[2];
    g_rpt[(nh0 + 9) * NROWP + r1] = d1[3];
}

// ---------------------------------------------------------------------------
// Kernel 2: gather (confirmed at the output-write floor; R8/R10 version).
// One block per (b, nh, tf, tp) 64x64 tile; vtab holds the 240 distinct
// output float4s; hot loop = 1 LDS.128 + 1 streaming STG.128.
//   idx = (t_f + t_p)*225 + (hf-hp+7)*15 + (wf-wp+7)
// ---------------------------------------------------------------------------
__global__ void __launch_bounds__(256) gather_kernel(
    const int* __restrict__ ptc,     // [B, 8] (non-positive; time = -ptc)
    const int* __restrict__ ftc,     // [B, 8]
    float4* __restrict__ out)        // [B, 16, 512, 512] / 4
{
    __shared__ float4 vtab[240];     // [wf][dh+7][par] : wf*30 + dh7*2 + par
    const int tid = threadIdx.x;
    const int blk = blockIdx.x;
    const int tp = blk & 7;
    const int tf = (blk >> 3) & 7;
    const int nh = (blk >> 6) & 15;
    const int b  = blk >> 10;

    const int t_f =  __ldg(ftc + b * 8 + tf);
    const int t_p = -__ldg(ptc + b * 8 + tp);
    const float* __restrict__ src = g_rpt + nh * NROWP + (t_f + t_p) * 225;

    if (tid < 240) {
        const int wf  = tid / 30;
        const int rem = tid - wf * 30;
        const int dh7 = rem >> 1;
        const int par = rem & 1;                       // wp0 = par*4
        const int si  = dh7 * 15 + wf - par * 4 + 7;   // in [3, 224]
        vtab[tid] = make_float4(__ldg(src + si),     __ldg(src + si - 1),
                                __ldg(src + si - 2), __ldg(src + si - 3));
    }
    __syncthreads();

    const int c4    = tid & 15;
    const int fhw0  = tid >> 4;            // 0..15
    const int wf    = fhw0 & 7;
    const int b0    = fhw0 >> 3;           // 0 or 1
    const int hp    = c4 >> 1;
    const int par   = c4 & 1;
    const int base0 = wf * 30 + (b0 - hp + 7) * 2 + par;   // k=0 index

    float4* __restrict__ p =
        out + ((((b * NHEAD + nh) * 512 + tf * 64) * 512 + tp * 64) >> 2)
            + fhw0 * 128 + c4;

    #pragma unroll
    for (int k = 0; k < 4; k++) {
        __stcs(p, vtab[base0 + 4 * k]);    // hf = b0 + 2k, always <= 7
        p += 2048;                          // fhw += 16
    }
}

// ---------------------------------------------------------------------------
// Launch. Input order: ptc, ftc, W1, b1, W2, rct, rpi_table (unused).
// ---------------------------------------------------------------------------
extern "C" void kernel_launch(void* const* d_in, const int* in_sizes, int n_in,
                              void* d_out, int out_size)
{
    const int*   ptc = (const int*)  d_in[0];
    const int*   ftc = (const int*)  d_in[1];
    const float* W1  = (const float*)d_in[2];
    const float* b1  = (const float*)d_in[3];
    const float* W2  = (const float*)d_in[4];
    const float* rct = (const float*)d_in[5];

    // 175 blocks x 128 rows = 22400 (NROWP); rows >= NROW are never read.
    mlp_kernel<<<NROWP / 128, 256>>>(rct, W1, b1, W2);

    // 8192 blocks: one per (b, nh, tf, tp) 64x64 tile
    gather_kernel<<<8 * NHEAD * 8 * 8, 256>>>(ptc, ftc, (float4*)d_out);
}